// round 17
// baseline (speedup 1.0000x reference)
#include <cuda_runtime.h>
#include <cuda_fp16.h>
#include <cstdint>

namespace {

constexpr int Hc = 16, Sc = 2048, Dc = 64;
constexpr int BM = 128, BN = 64, NT = 128;   // 4 warps/CTA, m=32 per warp
constexpr int NTILES = Sc / BN;              // 32 total; 16 per z-split CTA
constexpr int TZ = 2;                        // split-K factor over key tiles

// smem: Q staging (fp16, 16 KB), K/V 3-stage ring (16 KB/stage) => 64 KB -> 3 CTAs/SM
constexpr int QHI = 0;
constexpr int STG0 = 16384, STG_SZ = 16384;  // stage: KH +0, VH +8192
constexpr int KH_OF = 0, VH_OF = 8192;
constexpr int SMEM_BYTES = STG0 + 3 * STG_SZ;   // 65536

constexpr size_t PLANE = (size_t)2 * Hc * Sc * Dc;   // 4,194,304 elems
constexpr size_t ROWS_ALL = (size_t)2 * Hc * Sc;     // 65,536 rows

// scratch: pre-converted K (fp16, [bh][d][s]) and V (fp16, [bh][s][d])
__device__ __half g_kh[PLANE], g_vh[PLANE];
// split-K partials: unnormalized O and row sums, per z
__device__ float g_opart[TZ * PLANE];        // 33.5 MB
__device__ float g_rspart[TZ * ROWS_ALL];    // 0.5 MB

__device__ __forceinline__ float qscale() { return 0.125f * 1.4426950408889634f; }

__device__ __forceinline__ uint32_t swz(uint32_t o) { return o ^ ((o >> 3) & 0x70); }
__device__ __forceinline__ uint32_t s2u(const void* p) {
    uint32_t a;
    asm("{ .reg .u64 t; cvta.to.shared.u64 t, %1; cvt.u32.u64 %0, t; }" : "=r"(a) : "l"(p));
    return a;
}
__device__ __forceinline__ void cpasync16(uint32_t dst, const void* src) {
    asm volatile("cp.async.cg.shared.global [%0], [%1], 16;" :: "r"(dst), "l"(src));
}
__device__ __forceinline__ void ldsm4(uint32_t* r, uint32_t a) {
    asm volatile("ldmatrix.sync.aligned.m8n8.x4.shared.b16 {%0,%1,%2,%3}, [%4];"
                 : "=r"(r[0]), "=r"(r[1]), "=r"(r[2]), "=r"(r[3]) : "r"(a));
}
__device__ __forceinline__ void ldsm4t(uint32_t* r, uint32_t a) {
    asm volatile("ldmatrix.sync.aligned.m8n8.x4.trans.shared.b16 {%0,%1,%2,%3}, [%4];"
                 : "=r"(r[0]), "=r"(r[1]), "=r"(r[2]), "=r"(r[3]) : "r"(a));
}
// fp32-accumulator MMA (GEMM2)
__device__ __forceinline__ void mma_f16(float* d, const uint32_t* a, const uint32_t* b) {
    asm volatile("mma.sync.aligned.m16n8k16.row.col.f32.f16.f16.f32 "
                 "{%0,%1,%2,%3}, {%4,%5,%6,%7}, {%8,%9}, {%0,%1,%2,%3};"
                 : "+f"(d[0]), "+f"(d[1]), "+f"(d[2]), "+f"(d[3])
                 : "r"(a[0]), "r"(a[1]), "r"(a[2]), "r"(a[3]), "r"(b[0]), "r"(b[1]));
}
// fp16-accumulator MMA (GEMM1; output is ready-packed f16x2)
__device__ __forceinline__ void mma_f16acc(uint32_t* d, const uint32_t* a, const uint32_t* b) {
    asm volatile("mma.sync.aligned.m16n8k16.row.col.f16.f16.f16.f16 "
                 "{%0,%1}, {%2,%3,%4,%5}, {%6,%7}, {%0,%1};"
                 : "+r"(d[0]), "+r"(d[1])
                 : "r"(a[0]), "r"(a[1]), "r"(a[2]), "r"(a[3]), "r"(b[0]), "r"(b[1]));
}
__device__ __forceinline__ uint32_t ex2h2(uint32_t x) {
    uint32_t r;
    asm("ex2.approx.f16x2 %0, %1;" : "=r"(r) : "r"(x));
    return r;
}
__device__ __forceinline__ uint32_t hadd2u(uint32_t a, uint32_t b) {
    uint32_t r;
    asm("add.f16x2 %0, %1, %2;" : "=r"(r) : "r"(a), "r"(b));
    return r;
}

// ---------------- pre-pass: fp32 -> fp16 (K, V) ----------------
__global__ void cvt_kv(const float* __restrict__ K, const float* __restrict__ V)
{
    size_t i = ((size_t)blockIdx.x * 256 + threadIdx.x) * 4;
    float4 k4 = *(const float4*)(K + i);
    float4 v4 = *(const float4*)(V + i);
    *(__half2*)(g_kh + i)     = __floats2half2_rn(k4.x, k4.y);
    *(__half2*)(g_kh + i + 2) = __floats2half2_rn(k4.z, k4.w);
    *(__half2*)(g_vh + i)     = __floats2half2_rn(v4.x, v4.y);
    *(__half2*)(g_vh + i + 2) = __floats2half2_rn(v4.z, v4.w);
}

// ---------------- combine: out = (O0 + O1) / (rs0 + rs1) ----------------
__global__ void combine(float* __restrict__ out)
{
    size_t i = ((size_t)blockIdx.x * 256 + threadIdx.x) * 4;   // element index
    size_t row = i >> 6;                                        // /64 (Dc)
    float inv = 1.0f / (g_rspart[row] + g_rspart[ROWS_ALL + row]);
    float4 a = *(const float4*)(g_opart + i);
    float4 c = *(const float4*)(g_opart + PLANE + i);
    float4 r;
    r.x = (a.x + c.x) * inv;
    r.y = (a.y + c.y) * inv;
    r.z = (a.z + c.z) * inv;
    r.w = (a.w + c.w) * inv;
    *(float4*)(out + i) = r;
}

// ---------------- main: warp-MMA flash attention, m=32/warp, split-K z=2 ----------------
__global__ __launch_bounds__(NT, 3)
void attn_mma(const float* __restrict__ Q, const int* __restrict__ mask)
{
    extern __shared__ char smp[];
    const uint32_t sb = s2u(smp);
    const int tid = threadIdx.x, wid = tid >> 5, lid = tid & 31;
    const int bh = blockIdx.y, b = bh >> 4, m0 = blockIdx.x * BM;
    const int tz = blockIdx.z;
    const int tbeg = tz * (NTILES / TZ);
    const int NLT = NTILES / TZ;                   // 16 local tiles

    const float* Qb = Q + (size_t)bh * Sc * Dc;
    const size_t kvbase = (size_t)bh * Sc * Dc;
    float* Op = g_opart + (size_t)tz * PLANE + (size_t)bh * Sc * Dc;
    float* Rp = g_rspart + (size_t)tz * ROWS_ALL + (size_t)bh * Sc;

    // per-thread cp.async coordinates: 4 chunks each for K and V (64 rows x 8 chunks)
    const int r0 = tid >> 3, c0 = tid & 7;
    uint32_t dsw[4];
    #pragma unroll
    for (int i = 0; i < 4; ++i)
        dsw[i] = swz((uint32_t)((r0 + 16 * i) * 128 + c0 * 16));

    // prefetch local tiles 0..1 into stages 0..1
    #pragma unroll
    for (int pt = 0; pt < 2; ++pt) {
        const int t0 = (tbeg + pt) * BN;
        uint32_t st = sb + STG0 + pt * STG_SZ;
        #pragma unroll
        for (int i = 0; i < 4; ++i) {
            int r = r0 + 16 * i;
            cpasync16(st + KH_OF + dsw[i], g_kh + kvbase + (size_t)r * Sc + t0 + c0 * 8);
            cpasync16(st + VH_OF + dsw[i], g_vh + kvbase + (size_t)(t0 + r) * Dc + c0 * 8);
        }
        asm volatile("cp.async.commit_group;" ::: "memory");
    }

    // ---- Q: load fp32, fold (0.125*log2e)*mask, fp16 into swizzled smem (128 rows) ----
    #pragma unroll
    for (int i = 0; i < 8; ++i) {
        int idx = tid + NT * i;          // 0..1023
        int m = idx >> 3, c8 = idx & 7;
        const float4* qp = (const float4*)(Qb + (size_t)(m0 + m) * Dc + c8 * 8);
        float4 x = qp[0], y = qp[1];
        float sc = (mask[b * Sc + m0 + m] != 0) ? qscale() : 0.0f;
        __half2 h0 = __floats2half2_rn(x.x * sc, x.y * sc);
        __half2 h1 = __floats2half2_rn(x.z * sc, x.w * sc);
        __half2 h2 = __floats2half2_rn(y.x * sc, y.y * sc);
        __half2 h3 = __floats2half2_rn(y.z * sc, y.w * sc);
        uint32_t sw = swz((uint32_t)(m * 128 + c8 * 16));
        *(__half2*)(smp + QHI + sw)      = h0;
        *(__half2*)(smp + QHI + sw + 4)  = h1;
        *(__half2*)(smp + QHI + sw + 8)  = h2;
        *(__half2*)(smp + QHI + sw + 12) = h3;
    }
    __syncthreads();   // Q published

    // ---- hoist Q fragments (tile-invariant): 2 m-frags x 4 kk ----
    uint32_t ah[4][2][4];
    #pragma unroll
    for (int kk = 0; kk < 4; ++kk)
        #pragma unroll
        for (int mf = 0; mf < 2; ++mf) {
            uint32_t qa = (uint32_t)((wid * 32 + mf * 16 + (lid & 15)) * 128 +
                                     (lid >> 4) * 16 + kk * 32);
            ldsm4(ah[kk][mf], sb + QHI + swz(qa));
        }

    float Oa[2][8][4];
    #pragma unroll
    for (int mf = 0; mf < 2; ++mf)
        #pragma unroll
        for (int j = 0; j < 8; ++j)
            #pragma unroll
            for (int c = 0; c < 4; ++c) Oa[mf][j][c] = 0.0f;
    float rs[4] = {0.0f, 0.0f, 0.0f, 0.0f};   // rows: mf*16 + {lid>>2, lid>>2+8}

    const uint32_t b_row = (uint32_t)(((lid >> 3) & 1) * 8 + (lid & 7));
    const uint32_t b_col = (uint32_t)(((lid >> 4) & 1) * 16);

    // lt = LOCAL tile index (ring stages are indexed by lt, matching the prologue)
    for (int lt = 0; lt < NLT; ++lt) {
        if (lt + 1 < NLT) asm volatile("cp.async.wait_group 1;" ::: "memory");
        else              asm volatile("cp.async.wait_group 0;" ::: "memory");
        __syncthreads();   // publishes local tile lt; retires readers of stage (lt+2)%3

        // prefetch local tile lt+2 into stage (lt+2)%3
        if (lt + 2 < NLT) {
            const int t2 = (tbeg + lt + 2) * BN;
            uint32_t st = sb + STG0 + ((lt + 2) % 3) * STG_SZ;
            #pragma unroll
            for (int i = 0; i < 4; ++i) {
                int r = r0 + 16 * i;
                cpasync16(st + KH_OF + dsw[i], g_kh + kvbase + (size_t)r * Sc + t2 + c0 * 8);
                cpasync16(st + VH_OF + dsw[i], g_vh + kvbase + (size_t)(t2 + r) * Dc + c0 * 8);
            }
            asm volatile("cp.async.commit_group;" ::: "memory");
        }

        const uint32_t st = sb + STG0 + (lt % 3) * STG_SZ;
        const uint32_t kho = st + KH_OF, vho = st + VH_OF;

        uint32_t accs[4] = {0u, 0u, 0u, 0u};

        // ---- jp-sliced: [V-ldsm, GEMM1 f16acc (m32 x n16), ex2, GEMM2 partial] ----
        #pragma unroll
        for (int jp = 0; jp < 4; ++jp) {
            uint32_t vh2[4][4];
            #pragma unroll
            for (int jp2 = 0; jp2 < 4; ++jp2) {
                uint32_t va = swz((uint32_t)((jp * 16 + b_row) * 128 + jp2 * 32) + b_col);
                ldsm4t(vh2[jp2], vho + va);
            }

            // GEMM1 fp16-acc: Sd[mf] = {n-blk0 r, n-blk0 r+8, n-blk1 r, n-blk1 r+8}
            uint32_t Sd[2][4] = {{0u,0u,0u,0u},{0u,0u,0u,0u}};
            #pragma unroll
            for (int kk = 0; kk < 4; ++kk) {
                uint32_t bh2[4];
                uint32_t ka = swz((uint32_t)((kk * 16 + b_row) * 128 + jp * 32) + b_col);
                ldsm4t(bh2, kho + ka);
                #pragma unroll
                for (int mf = 0; mf < 2; ++mf) {
                    mma_f16acc(Sd[mf],     ah[kk][mf], bh2);
                    mma_f16acc(Sd[mf] + 2, ah[kk][mf], bh2 + 2);
                }
            }

            // softmax: A = 2^S elementwise on f16x2 fragments (layout == A operand)
            uint32_t A[2][4];
            #pragma unroll
            for (int mf = 0; mf < 2; ++mf) {
                A[mf][0] = ex2h2(Sd[mf][0]);
                A[mf][1] = ex2h2(Sd[mf][1]);
                A[mf][2] = ex2h2(Sd[mf][2]);
                A[mf][3] = ex2h2(Sd[mf][3]);
                accs[mf * 2 + 0] = hadd2u(accs[mf * 2 + 0], hadd2u(A[mf][0], A[mf][2]));
                accs[mf * 2 + 1] = hadd2u(accs[mf * 2 + 1], hadd2u(A[mf][1], A[mf][3]));
            }

            // GEMM2 (fp32 accum): O[m32][64 d] += P(:, jp blk) * V(jp blk, :)
            #pragma unroll
            for (int jp2 = 0; jp2 < 4; ++jp2)
                #pragma unroll
                for (int mf = 0; mf < 2; ++mf) {
                    mma_f16(Oa[mf][2 * jp2],     A[mf], vh2[jp2]);
                    mma_f16(Oa[mf][2 * jp2 + 1], A[mf], vh2[jp2] + 2);
                }
        }

        #pragma unroll
        for (int i = 0; i < 4; ++i) {
            float2 a = __half22float2(*(__half2*)&accs[i]);
            rs[i] += a.x + a.y;
        }
    }

    // ---- reduce row sums across 4 lanes; write UNNORMALIZED partials to scratch ----
    #pragma unroll
    for (int i = 0; i < 4; ++i) {
        rs[i] += __shfl_xor_sync(0xffffffffu, rs[i], 1);
        rs[i] += __shfl_xor_sync(0xffffffffu, rs[i], 2);
    }

    const int colb = (lid & 3) * 2;
    #pragma unroll
    for (int mf = 0; mf < 2; ++mf) {
        const int row = m0 + wid * 32 + mf * 16 + (lid >> 2);
        if ((lid & 3) == 0) {
            Rp[row]     = rs[mf * 2 + 0];
            Rp[row + 8] = rs[mf * 2 + 1];
        }
        float* Op0 = Op + (size_t)row * Dc;
        float* Op1 = Op0 + 8 * Dc;
        #pragma unroll
        for (int nf = 0; nf < 8; ++nf) {
            *(float2*)(Op0 + 8 * nf + colb) = make_float2(Oa[mf][nf][0], Oa[mf][nf][1]);
            *(float2*)(Op1 + 8 * nf + colb) = make_float2(Oa[mf][nf][2], Oa[mf][nf][3]);
        }
    }
}

} // namespace

extern "C" void kernel_launch(void* const* d_in, const int* in_sizes, int n_in,
                              void* d_out, int out_size)
{
    const float* q    = (const float*)d_in[0];
    const float* k    = (const float*)d_in[1];
    const float* v    = (const float*)d_in[2];
    const int*   mask = (const int*)d_in[3];
    float*       out  = (float*)d_out;

    cvt_kv<<<(int)(PLANE / 4 / 256), 256>>>(k, v);

    cudaFuncSetAttribute(attn_mma, cudaFuncAttributeMaxDynamicSharedMemorySize, SMEM_BYTES);
    dim3 grid(Sc / BM, 2 * Hc, TZ);   // (16, 32, 2) = 1024 CTAs of 128 threads
    attn_mma<<<grid, NT, SMEM_BYTES>>>(q, mask);

    combine<<<(int)(PLANE / 4 / 256), 256>>>(out);
}